// round 1
// baseline (speedup 1.0000x reference)
#include <cuda_runtime.h>
#include <math_constants.h>

// Problem constants
#define B 32
#define S 2048
#define H 1024

#define NSPLIT 16          // S-splits per batch
#define CH (S / NSPLIT)    // 128 rows per block
#define TROWS 16           // rows per SMEM tile
#define NTILES (CH / TROWS) // 8

#define KSLICES 8
#define KCH (H / KSLICES)  // 128
#define BG 4               // batches per q-block
#define HSLICE 256         // h per q-block

// Scratch (no cudaMalloc allowed)
__device__ float  g_qpart[KSLICES * B * H];          // 1 MB   partial q = h_t @ W
__device__ float4 g_pacc[B * NSPLIT * (H / 4)];      // 2 MB   per-split weighted sums
__device__ float  g_ml[B * NSPLIT * 2];              // per-split (m, l)

// ---------------------------------------------------------------------------
// Kernel 1: partial q[b,h] = sum_{k in slice} h_t[b,k] * W[k,h]
// grid (H/HSLICE=4, KSLICES=8, B/BG=8), 256 threads
// ---------------------------------------------------------------------------
__global__ void qpart_kernel(const float* __restrict__ h_t,
                             const float* __restrict__ W)
{
    __shared__ float hs[BG][KCH];
    const int tid = threadIdx.x;
    const int h   = blockIdx.x * HSLICE + tid;
    const int k0  = blockIdx.y * KCH;
    const int bg  = blockIdx.z;

    // load h_t slice: BG*KCH = 512 floats
    for (int i = tid; i < BG * KCH; i += blockDim.x) {
        int j  = i / KCH;
        int kk = i % KCH;
        hs[j][kk] = h_t[(bg * BG + j) * H + k0 + kk];
    }
    __syncthreads();

    float acc0 = 0.f, acc1 = 0.f, acc2 = 0.f, acc3 = 0.f;
    #pragma unroll 4
    for (int kk = 0; kk < KCH; kk++) {
        float w = W[(k0 + kk) * H + h];
        acc0 = fmaf(hs[0][kk], w, acc0);
        acc1 = fmaf(hs[1][kk], w, acc1);
        acc2 = fmaf(hs[2][kk], w, acc2);
        acc3 = fmaf(hs[3][kk], w, acc3);
    }
    const int pbase = blockIdx.y * B;
    g_qpart[(pbase + bg * BG + 0) * H + h] = acc0;
    g_qpart[(pbase + bg * BG + 1) * H + h] = acc1;
    g_qpart[(pbase + bg * BG + 2) * H + h] = acc2;
    g_qpart[(pbase + bg * BG + 3) * H + h] = acc3;
}

// ---------------------------------------------------------------------------
// Kernel 2: per-(b, split) online-softmax weighted sum over CH rows of cntx.
// grid (NSPLIT, B), 256 threads.
// dyn smem: q[1024] + tile[TROWS*1024] + scores[TROWS]
// ---------------------------------------------------------------------------
#define SMEM_FLOATS (H + TROWS * H + TROWS)

__global__ __launch_bounds__(256) void split_kernel(const float* __restrict__ cntx)
{
    extern __shared__ float sm[];
    float*  q_s    = sm;                 // 1024
    float*  tile   = sm + H;             // TROWS*1024
    float*  scores = sm + H + TROWS * H; // TROWS
    float4* tile4  = reinterpret_cast<float4*>(tile);
    const float4* q4 = reinterpret_cast<const float4*>(q_s);

    const int tid  = threadIdx.x;
    const int b    = blockIdx.y;
    const int sp   = blockIdx.x;
    const int s0   = sp * CH;
    const int wid  = tid >> 5;
    const int lane = tid & 31;

    // q[b,:] = sum of KSLICES partials (deterministic reduction)
    for (int idx = tid; idx < H; idx += 256) {
        float v = 0.f;
        #pragma unroll
        for (int p = 0; p < KSLICES; p++)
            v += g_qpart[(p * B + b) * H + idx];
        q_s[idx] = v;
    }
    __syncthreads();

    float m = -1e30f, l = 0.f;
    float4 acc = make_float4(0.f, 0.f, 0.f, 0.f);

    for (int t = 0; t < NTILES; t++) {
        const float4* src = reinterpret_cast<const float4*>(
            cntx + ((size_t)(b * S + s0 + t * TROWS)) * H);
        // load 16 rows (16 KB ... 64 KB): 16*256 float4 units, coalesced
        #pragma unroll
        for (int i = 0; i < TROWS; i++)
            tile4[i * 256 + tid] = src[i * 256 + tid];
        __syncthreads();

        // scores: warp w handles rows 2w, 2w+1
        #pragma unroll
        for (int r = 0; r < 2; r++) {
            int srow = 2 * wid + r;
            float p = 0.f;
            #pragma unroll
            for (int j = 0; j < 8; j++) {
                float4 v = tile4[srow * 256 + lane + 32 * j];
                float4 qv = q4[lane + 32 * j];
                p = fmaf(v.x, qv.x, p);
                p = fmaf(v.y, qv.y, p);
                p = fmaf(v.z, qv.z, p);
                p = fmaf(v.w, qv.w, p);
            }
            #pragma unroll
            for (int off = 16; off > 0; off >>= 1)
                p += __shfl_xor_sync(0xffffffffu, p, off);
            if (lane == 0) scores[srow] = p;
        }
        __syncthreads();

        // online softmax update (all threads compute identically)
        float mnew = m;
        #pragma unroll
        for (int s = 0; s < TROWS; s++) mnew = fmaxf(mnew, scores[s]);
        float corr = __expf(m - mnew);
        acc.x *= corr; acc.y *= corr; acc.z *= corr; acc.w *= corr;
        l *= corr;
        float w[TROWS];
        #pragma unroll
        for (int s = 0; s < TROWS; s++) {
            w[s] = __expf(scores[s] - mnew);
            l += w[s];
        }
        m = mnew;

        // accumulate weighted rows from the SAME smem tile
        #pragma unroll
        for (int s = 0; s < TROWS; s++) {
            float4 v = tile4[s * 256 + tid];
            acc.x = fmaf(w[s], v.x, acc.x);
            acc.y = fmaf(w[s], v.y, acc.y);
            acc.z = fmaf(w[s], v.z, acc.z);
            acc.w = fmaf(w[s], v.w, acc.w);
        }
        __syncthreads();  // guard tile + scores reuse
    }

    g_pacc[(b * NSPLIT + sp) * 256 + tid] = acc;
    if (tid == 0) {
        g_ml[(b * NSPLIT + sp) * 2 + 0] = m;
        g_ml[(b * NSPLIT + sp) * 2 + 1] = l;
    }
}

// ---------------------------------------------------------------------------
// Kernel 3: combine splits + epilogue. grid (B), 256 threads.
// ---------------------------------------------------------------------------
__global__ void combine_kernel(const float* __restrict__ h_t,
                               const float* __restrict__ alpha,
                               const float* __restrict__ beta,
                               float* __restrict__ out)
{
    const int tid = threadIdx.x;
    const int b   = blockIdx.x;

    // global max / sum (all threads redundantly, 16 iterations)
    float M = -1e30f;
    #pragma unroll
    for (int i = 0; i < NSPLIT; i++)
        M = fmaxf(M, g_ml[(b * NSPLIT + i) * 2 + 0]);
    float L = 0.f;
    float wsc[NSPLIT];
    #pragma unroll
    for (int i = 0; i < NSPLIT; i++) {
        float mi = g_ml[(b * NSPLIT + i) * 2 + 0];
        float li = g_ml[(b * NSPLIT + i) * 2 + 1];
        wsc[i] = __expf(mi - M);
        L += li * wsc[i];
    }

    float4 o = make_float4(0.f, 0.f, 0.f, 0.f);
    #pragma unroll
    for (int i = 0; i < NSPLIT; i++) {
        float4 p = g_pacc[(b * NSPLIT + i) * 256 + tid];
        o.x = fmaf(wsc[i], p.x, o.x);
        o.y = fmaf(wsc[i], p.y, o.y);
        o.z = fmaf(wsc[i], p.z, o.z);
        o.w = fmaf(wsc[i], p.w, o.w);
    }
    float a  = alpha[0];
    float bt = beta[0] / L;
    const float4* ht4 = reinterpret_cast<const float4*>(h_t);
    float4 hv = ht4[b * 256 + tid];
    float4 res;
    res.x = fmaf(a, hv.x, bt * o.x);
    res.y = fmaf(a, hv.y, bt * o.y);
    res.z = fmaf(a, hv.z, bt * o.z);
    res.w = fmaf(a, hv.w, bt * o.w);
    reinterpret_cast<float4*>(out)[b * 256 + tid] = res;
}

// ---------------------------------------------------------------------------
extern "C" void kernel_launch(void* const* d_in, const int* in_sizes, int n_in,
                              void* d_out, int out_size)
{
    const float* h_t   = (const float*)d_in[0];
    const float* cntx  = (const float*)d_in[1];
    const float* W     = (const float*)d_in[2];
    const float* alpha = (const float*)d_in[3];
    const float* beta  = (const float*)d_in[4];
    float* out = (float*)d_out;

    const int smem_bytes = SMEM_FLOATS * (int)sizeof(float); // ~69.7 KB
    cudaFuncSetAttribute(split_kernel,
                         cudaFuncAttributeMaxDynamicSharedMemorySize, smem_bytes);

    qpart_kernel<<<dim3(H / HSLICE, KSLICES, B / BG), 256>>>(h_t, W);
    split_kernel<<<dim3(NSPLIT, B), 256, smem_bytes>>>(cntx);
    combine_kernel<<<B, 256>>>(h_t, alpha, beta, out);
}

// round 2
// speedup vs baseline: 1.3361x; 1.3361x over previous
#include <cuda_runtime.h>

// Problem constants
#define B 32
#define S 2048
#define H 1024

// ---- split-softmax config ----
#define NSPLIT 32            // S-splits per batch
#define CH (S / NSPLIT)      // 64 rows per CTA
#define TROWS 8              // rows per SMEM tile
#define NTILES (CH / TROWS)  // 8

// ---- q GEMV config ----
#define KSLICES 16
#define KCH (H / KSLICES)    // 64
#define BG 8                 // batches per q-block
#define HSLICE 256

// Scratch (no cudaMalloc allowed)
__device__ float  g_qpart[KSLICES * B * H];          // 2 MB
__device__ float4 g_pacc[B * NSPLIT * (H / 4)];      // 4 MB
__device__ float  g_ml[B * NSPLIT * 2];

// ---------------------------------------------------------------------------
// cp.async helpers
// ---------------------------------------------------------------------------
__device__ __forceinline__ unsigned smem_u32(const void* p) {
    return (unsigned)__cvta_generic_to_shared(p);
}
__device__ __forceinline__ void cp_async16(unsigned dst, const void* src) {
    asm volatile("cp.async.cg.shared.global [%0], [%1], 16;\n"
                 :: "r"(dst), "l"(src));
}
__device__ __forceinline__ void cp_commit() {
    asm volatile("cp.async.commit_group;\n" ::: "memory");
}
template <int N>
__device__ __forceinline__ void cp_wait() {
    asm volatile("cp.async.wait_group %0;\n" :: "n"(N) : "memory");
}

// ---------------------------------------------------------------------------
// Kernel 1: partial q[b,h] = sum_{k in slice} h_t[b,k] * W[k,h]
// grid (H/HSLICE=4, KSLICES=16, B/BG=4), 256 threads
// Each thread: one h column, 8 batch accumulators, 64 W loads (deep unroll).
// ---------------------------------------------------------------------------
__global__ __launch_bounds__(256) void qpart_kernel(const float* __restrict__ h_t,
                                                    const float* __restrict__ W)
{
    __shared__ float hs[BG][KCH];
    const int tid = threadIdx.x;
    const int h   = blockIdx.x * HSLICE + tid;
    const int k0  = blockIdx.y * KCH;
    const int bg  = blockIdx.z;

    // load h_t slice: BG*KCH = 512 floats
    for (int i = tid; i < BG * KCH; i += 256) {
        int j  = i / KCH;
        int kk = i % KCH;
        hs[j][kk] = h_t[(bg * BG + j) * H + k0 + kk];
    }
    __syncthreads();

    float acc[BG];
    #pragma unroll
    for (int j = 0; j < BG; j++) acc[j] = 0.f;

    const float* wp = W + (size_t)k0 * H + h;
    #pragma unroll 16
    for (int kk = 0; kk < KCH; kk++) {
        float w = wp[(size_t)kk * H];
        #pragma unroll
        for (int j = 0; j < BG; j++)
            acc[j] = fmaf(hs[j][kk], w, acc[j]);
    }
    #pragma unroll
    for (int j = 0; j < BG; j++)
        g_qpart[((size_t)blockIdx.y * B + bg * BG + j) * H + h] = acc[j];
}

// ---------------------------------------------------------------------------
// Kernel 2: per-(b, split) online-softmax weighted sum over CH rows of cntx,
// cp.async double-buffered. grid (NSPLIT, B), 256 threads.
// dyn smem: q[1024] + 2 * TROWS*1024 + scores[TROWS]  (~68 KB)
// ---------------------------------------------------------------------------
#define SMEM_FLOATS (H + 2 * TROWS * H + TROWS)

__global__ __launch_bounds__(256) void split_kernel(const float* __restrict__ cntx)
{
    extern __shared__ float sm[];
    float* q_s    = sm;                      // 1024
    float* bufs   = sm + H;                  // 2 * TROWS*1024
    float* scores = sm + H + 2 * TROWS * H;  // TROWS
    const float4* q4 = reinterpret_cast<const float4*>(q_s);

    const int tid  = threadIdx.x;
    const int b    = blockIdx.y;
    const int sp   = blockIdx.x;
    const int wid  = tid >> 5;
    const int lane = tid & 31;

    const float* base = cntx + ((size_t)b * S + (size_t)sp * CH) * H;

    // issue tile t into buffer buf (8 rows x 1024 floats, 16B per cp.async)
    auto issue = [&](int t, int buf) {
        const char* src = (const char*)(base + (size_t)t * TROWS * H) + tid * 16;
        unsigned dst = smem_u32(bufs) + (unsigned)buf * (TROWS * H * 4) + tid * 16;
        #pragma unroll
        for (int i = 0; i < TROWS; i++)
            cp_async16(dst + i * (H * 4), src + i * (size_t)(H * 4));
        cp_commit();
    };

    issue(0, 0);
    issue(1, 1);

    // q[b,:] = sum of KSLICES partials (overlaps with prefetch of tiles 0,1)
    for (int idx = tid; idx < H; idx += 256) {
        float v = 0.f;
        #pragma unroll
        for (int p = 0; p < KSLICES; p++)
            v += g_qpart[((size_t)p * B + b) * H + idx];
        q_s[idx] = v;
    }

    float m = -1e30f, l = 0.f;
    float4 acc = make_float4(0.f, 0.f, 0.f, 0.f);

    for (int t = 0; t < NTILES; t++) {
        if (t + 1 < NTILES) cp_wait<1>(); else cp_wait<0>();
        __syncthreads();

        const float4* t4 = reinterpret_cast<const float4*>(
            bufs + (size_t)(t & 1) * (TROWS * H));

        // scores: warp wid handles row wid
        {
            float p = 0.f;
            #pragma unroll
            for (int j = 0; j < 8; j++) {
                float4 v  = t4[wid * 256 + lane + 32 * j];
                float4 qv = q4[lane + 32 * j];
                p = fmaf(v.x, qv.x, p);
                p = fmaf(v.y, qv.y, p);
                p = fmaf(v.z, qv.z, p);
                p = fmaf(v.w, qv.w, p);
            }
            #pragma unroll
            for (int off = 16; off > 0; off >>= 1)
                p += __shfl_xor_sync(0xffffffffu, p, off);
            if (lane == 0) scores[wid] = p;
        }
        __syncthreads();

        // online softmax update (all threads identical)
        float mnew = m;
        #pragma unroll
        for (int s = 0; s < TROWS; s++) mnew = fmaxf(mnew, scores[s]);
        float corr = __expf(m - mnew);
        acc.x *= corr; acc.y *= corr; acc.z *= corr; acc.w *= corr;
        l *= corr;
        float w[TROWS];
        #pragma unroll
        for (int s = 0; s < TROWS; s++) {
            w[s] = __expf(scores[s] - mnew);
            l += w[s];
        }
        m = mnew;

        // accumulate weighted rows from the same smem tile
        #pragma unroll
        for (int s = 0; s < TROWS; s++) {
            float4 v = t4[s * 256 + tid];
            acc.x = fmaf(w[s], v.x, acc.x);
            acc.y = fmaf(w[s], v.y, acc.y);
            acc.z = fmaf(w[s], v.z, acc.z);
            acc.w = fmaf(w[s], v.w, acc.w);
        }
        __syncthreads();  // tile + scores fully consumed

        if (t + 2 < NTILES) issue(t + 2, t & 1);
    }

    g_pacc[((size_t)b * NSPLIT + sp) * 256 + tid] = acc;
    if (tid == 0) {
        g_ml[(b * NSPLIT + sp) * 2 + 0] = m;
        g_ml[(b * NSPLIT + sp) * 2 + 1] = l;
    }
}

// ---------------------------------------------------------------------------
// Kernel 3: combine splits + epilogue. grid (B), 256 threads.
// ---------------------------------------------------------------------------
__global__ void combine_kernel(const float* __restrict__ h_t,
                               const float* __restrict__ alpha,
                               const float* __restrict__ beta,
                               float* __restrict__ out)
{
    const int tid = threadIdx.x;
    const int b   = blockIdx.x;

    float M = -1e30f;
    #pragma unroll
    for (int i = 0; i < NSPLIT; i++)
        M = fmaxf(M, g_ml[(b * NSPLIT + i) * 2 + 0]);
    float L = 0.f;
    float wsc[NSPLIT];
    #pragma unroll
    for (int i = 0; i < NSPLIT; i++) {
        float mi = g_ml[(b * NSPLIT + i) * 2 + 0];
        float li = g_ml[(b * NSPLIT + i) * 2 + 1];
        wsc[i] = __expf(mi - M);
        L += li * wsc[i];
    }

    float4 o = make_float4(0.f, 0.f, 0.f, 0.f);
    #pragma unroll
    for (int i = 0; i < NSPLIT; i++) {
        float4 p = g_pacc[((size_t)b * NSPLIT + i) * 256 + tid];
        o.x = fmaf(wsc[i], p.x, o.x);
        o.y = fmaf(wsc[i], p.y, o.y);
        o.z = fmaf(wsc[i], p.z, o.z);
        o.w = fmaf(wsc[i], p.w, o.w);
    }
    float a  = alpha[0];
    float bt = beta[0] / L;
    const float4* ht4 = reinterpret_cast<const float4*>(h_t);
    float4 hv = ht4[b * 256 + tid];
    float4 res;
    res.x = fmaf(a, hv.x, bt * o.x);
    res.y = fmaf(a, hv.y, bt * o.y);
    res.z = fmaf(a, hv.z, bt * o.z);
    res.w = fmaf(a, hv.w, bt * o.w);
    reinterpret_cast<float4*>(out)[b * 256 + tid] = res;
}

// ---------------------------------------------------------------------------
extern "C" void kernel_launch(void* const* d_in, const int* in_sizes, int n_in,
                              void* d_out, int out_size)
{
    const float* h_t   = (const float*)d_in[0];
    const float* cntx  = (const float*)d_in[1];
    const float* W     = (const float*)d_in[2];
    const float* alpha = (const float*)d_in[3];
    const float* beta  = (const float*)d_in[4];
    float* out = (float*)d_out;

    const int smem_bytes = SMEM_FLOATS * (int)sizeof(float); // ~68.2 KB
    cudaFuncSetAttribute(split_kernel,
                         cudaFuncAttributeMaxDynamicSharedMemorySize, smem_bytes);

    qpart_kernel<<<dim3(H / HSLICE, KSLICES, B / BG), 256>>>(h_t, W);
    split_kernel<<<dim3(NSPLIT, B), 256, smem_bytes>>>(cntx);
    combine_kernel<<<B, 256>>>(h_t, alpha, beta, out);
}